// round 15
// baseline (speedup 1.0000x reference)
#include <cuda_runtime.h>
#include <cuda_fp16.h>
#include <cuda_bf16.h>

#define N_NODES 100000
#define N_EDGES 3200000
#define F_IN 35
#define KPAD 36
#define F_HID 64
#define F_OUT 2
#define FIXP 268435456.0f   // 2^28
#define FIXP_INV (1.0f / 268435456.0f)

// ---- scratch (static; no allocation allowed; zero-initialized at load) ----
__device__ __align__(16) __half g_h1[N_NODES * F_HID];  // dinv * (x@W1), fp16, row-major
__device__ __align__(16) float  g_h2[N_NODES * F_OUT];  // dinv * (layer-2 features)
__device__ unsigned long long g_acc[N_NODES];  // hi24: count, lo40: sum(ew)*2^28 (self-cleaned)
__device__ float g_dinv[N_NODES];
__device__ __align__(8) int2 g_seg[N_NODES];   // (beg, end) of node's CSR segment
__device__ int   g_cursor;                     // CSR cursor (self-cleaned by k_gemm_fill)
__device__ __align__(16) int g_rank[N_EDGES];  // per-edge slot within its dst segment
__device__ __align__(8) int2 g_csr[N_EDGES];   // (src byte-offset = src<<7, ew bits)

// ---------------- edge scatter (4 edges/thread): counts + weighted degree + rank ----
__global__ void __launch_bounds__(256) k_scatter(const int* __restrict__ ei,
                                                 const float* __restrict__ ew, int ne) {
    int e0 = (blockIdx.x * 256 + threadIdx.x) * 4;
    if (e0 + 3 < ne) {
        float4 w4 = *reinterpret_cast<const float4*>(ew + e0);  // e0 % 4 == 0
        int d0 = ei[ne + e0], d1 = ei[ne + e0 + 1];
        int d2 = ei[ne + e0 + 2], d3 = ei[ne + e0 + 3];
        unsigned long long o0 = atomicAdd(&g_acc[d0], (1ULL << 40) | (unsigned long long)(w4.x * FIXP));
        unsigned long long o1 = atomicAdd(&g_acc[d1], (1ULL << 40) | (unsigned long long)(w4.y * FIXP));
        unsigned long long o2 = atomicAdd(&g_acc[d2], (1ULL << 40) | (unsigned long long)(w4.z * FIXP));
        unsigned long long o3 = atomicAdd(&g_acc[d3], (1ULL << 40) | (unsigned long long)(w4.w * FIXP));
        *reinterpret_cast<int4*>(g_rank + e0) =
            make_int4((int)(o0 >> 40), (int)(o1 >> 40), (int)(o2 >> 40), (int)(o3 >> 40));
    } else {
        for (int e = e0; e < ne; e++) {
            int dst = ei[ne + e];
            unsigned long long old = atomicAdd(&g_acc[dst],
                (1ULL << 40) | (unsigned long long)(ew[e] * FIXP));
            g_rank[e] = (int)(old >> 40);
        }
    }
}

// ---- base: dinv + seg alloc (block scan + cursor atomic) + acc self-clean ----
__global__ void __launch_bounds__(256) k_base(int n) {
    __shared__ int swarp[8];
    __shared__ int sbase;
    int t = threadIdx.x, lane = t & 31, wid = t >> 5;
    int i = blockIdx.x * 256 + t;
    int c = 0;
    if (i < n) {
        unsigned long long a = g_acc[i];
        g_acc[i] = 0ULL;                    // self-clean for next replay
        c = (int)(a >> 40);
        float deg = 1.0f + (float)(a & ((1ULL << 40) - 1)) * FIXP_INV;
        g_dinv[i] = rsqrtf(deg);
    }
    int v = c;
#pragma unroll
    for (int o = 1; o < 32; o <<= 1) {
        int u = __shfl_up_sync(0xFFFFFFFFu, v, o);
        if (lane >= o) v += u;
    }
    if (lane == 31) swarp[wid] = v;
    __syncthreads();
    if (wid == 0) {
        int s = (lane < 8) ? swarp[lane] : 0;
#pragma unroll
        for (int o = 1; o < 8; o <<= 1) {
            int u = __shfl_up_sync(0xFFFFFFFFu, s, o);
            if (lane >= o) s += u;
        }
        if (lane < 8) swarp[lane] = s;
        if (lane == 7) sbase = atomicAdd(&g_cursor, s);
    }
    __syncthreads();
    int excl = v - c + (wid > 0 ? swarp[wid - 1] : 0);
    if (i < n) {
        int beg = sbase + excl;
        g_seg[i] = make_int2(beg, beg + c);
    }
}

// ---------------- fused: layer-1 GEMM (4 rows/warp, 2 cols/lane) || CSR fill ----
__global__ void __launch_bounds__(256) k_gemm_fill(
        const int* __restrict__ ei, const float* __restrict__ ew,
        const float* __restrict__ x, const float* __restrict__ W1,
        int n, int ne, int nblk_gm) {
    __shared__ float2 sW2[KPAD][32];      // [k][lane] -> cols (2l, 2l+1)
    __shared__ float  sx[8][4][KPAD];

    if (blockIdx.x >= (unsigned)nblk_gm) {
        // ---- CSR fill part (4 edges/thread): (src<<7, ew) ----
        if (blockIdx.x == (unsigned)nblk_gm && threadIdx.x == 0)
            g_cursor = 0;   // self-clean for next replay
        int e0 = ((blockIdx.x - nblk_gm) * 256 + threadIdx.x) * 4;
        if (e0 + 3 < ne) {
            int4   s4 = *reinterpret_cast<const int4*>(ei + e0);       // e0 % 4 == 0
            float4 w4 = *reinterpret_cast<const float4*>(ew + e0);
            int4   r4 = *reinterpret_cast<const int4*>(g_rank + e0);
            int d0 = ei[ne + e0], d1 = ei[ne + e0 + 1];
            int d2 = ei[ne + e0 + 2], d3 = ei[ne + e0 + 3];
            g_csr[g_seg[d0].x + r4.x] = make_int2(s4.x << 7, __float_as_int(w4.x));
            g_csr[g_seg[d1].x + r4.y] = make_int2(s4.y << 7, __float_as_int(w4.y));
            g_csr[g_seg[d2].x + r4.z] = make_int2(s4.z << 7, __float_as_int(w4.z));
            g_csr[g_seg[d3].x + r4.w] = make_int2(s4.w << 7, __float_as_int(w4.w));
        } else {
            for (int e = e0; e < ne; e++) {
                int src = ei[e];
                int dst = ei[ne + e];
                g_csr[g_seg[dst].x + g_rank[e]] = make_int2(src << 7, __float_as_int(ew[e]));
            }
        }
        return;
    }

    // ---- gemm1 part: h1' = dinv[row] * (x[row] @ W1), 4 rows/warp, 2 cols/lane ----
    int t = threadIdx.x, w = t >> 5, lane = t & 31;
    for (int i = t; i < KPAD * 32; i += 256) {
        int k = i >> 5, l = i & 31;
        float2 v = make_float2(0.f, 0.f);
        if (k < F_IN) { v.x = W1[k * F_HID + 2 * l]; v.y = W1[k * F_HID + 2 * l + 1]; }
        sW2[k][l] = v;
    }
    int row0 = blockIdx.x * 32 + w * 4;
#pragma unroll
    for (int r = 0; r < 4; r++) {
        int row = row0 + r;
        if (row < n) {
            sx[w][r][lane] = x[(size_t)row * F_IN + lane];
            if (lane < 4) sx[w][r][32 + lane] =
                (lane < F_IN - 32) ? x[(size_t)row * F_IN + 32 + lane] : 0.f;
        }
    }
    __syncthreads();
    if (row0 >= n) return;

    float a0x = 0.f, a0y = 0.f, a1x = 0.f, a1y = 0.f;
    float a2x = 0.f, a2y = 0.f, a3x = 0.f, a3y = 0.f;
    const float4* sx0 = reinterpret_cast<const float4*>(sx[w][0]);
    const float4* sx1 = reinterpret_cast<const float4*>(sx[w][1]);
    const float4* sx2 = reinterpret_cast<const float4*>(sx[w][2]);
    const float4* sx3 = reinterpret_cast<const float4*>(sx[w][3]);
#pragma unroll
    for (int k4 = 0; k4 < KPAD / 4; k4++) {
        float4 x0 = sx0[k4], x1 = sx1[k4], x2 = sx2[k4], x3 = sx3[k4];
#pragma unroll
        for (int i = 0; i < 4; i++) {
            float2 wv = sW2[k4 * 4 + i][lane];
            float v0 = (&x0.x)[i], v1 = (&x1.x)[i], v2 = (&x2.x)[i], v3 = (&x3.x)[i];
            a0x += v0 * wv.x; a0y += v0 * wv.y;
            a1x += v1 * wv.x; a1y += v1 * wv.y;
            a2x += v2 * wv.x; a2y += v2 * wv.y;
            a3x += v3 * wv.x; a3y += v3 * wv.y;
        }
    }
    {
        float dv = g_dinv[row0];
        reinterpret_cast<__half2*>(g_h1 + (size_t)row0 * F_HID)[lane] =
            __floats2half2_rn(dv * a0x, dv * a0y);
    }
    if (row0 + 1 < n) {
        float dv = g_dinv[row0 + 1];
        reinterpret_cast<__half2*>(g_h1 + (size_t)(row0 + 1) * F_HID)[lane] =
            __floats2half2_rn(dv * a1x, dv * a1y);
    }
    if (row0 + 2 < n) {
        float dv = g_dinv[row0 + 2];
        reinterpret_cast<__half2*>(g_h1 + (size_t)(row0 + 2) * F_HID)[lane] =
            __floats2half2_rn(dv * a2x, dv * a2y);
    }
    if (row0 + 3 < n) {
        float dv = g_dinv[row0 + 3];
        reinterpret_cast<__half2*>(g_h1 + (size_t)(row0 + 3) * F_HID)[lane] =
            __floats2half2_rn(dv * a3x, dv * a3y);
    }
}

// ---- agg1: 8 lanes/edge, LDG.128, 4 edges/warp-iter (x2 unroll) + relu + b1 + W2 GEMV ----
__global__ void __launch_bounds__(256) k_agg1(const float* __restrict__ W2,
                                              const float* __restrict__ b1, int n) {
    __shared__ int2 stage[8][32];
    int wi = threadIdx.x >> 5;
    int lane = threadIdx.x & 31;
    int h = lane >> 3;        // edge subgroup 0..3: handles edges i+h
    int q = lane & 7;         // col chunk: cols 8q..8q+7 (16 bytes)
    int w = blockIdx.x * 8 + wi;
    if (w >= n) return;
    int2 seg = g_seg[w];
    int beg = seg.x, end = seg.y;
    float dv = g_dinv[w];
    const char* h1b = reinterpret_cast<const char*>(g_h1) + (q << 4);

    float a0 = 0.f, a1 = 0.f, a2 = 0.f, a3 = 0.f;
    float a4 = 0.f, a5 = 0.f, a6 = 0.f, a7 = 0.f;
    if (h == 0) {   // self term in subgroup 0 only (subgroups summed at the end)
        uint4 sr = *reinterpret_cast<const uint4*>(h1b + ((size_t)w << 7));
        float2 f;
        f = __half22float2(*reinterpret_cast<const __half2*>(&sr.x)); a0 = f.x; a1 = f.y;
        f = __half22float2(*reinterpret_cast<const __half2*>(&sr.y)); a2 = f.x; a3 = f.y;
        f = __half22float2(*reinterpret_cast<const __half2*>(&sr.z)); a4 = f.x; a5 = f.y;
        f = __half22float2(*reinterpret_cast<const __half2*>(&sr.w)); a6 = f.x; a7 = f.y;
    }

#define ACC8(r, nm) do { \
        float2 _f; \
        _f = __half22float2(*reinterpret_cast<const __half2*>(&(r).x)); a0 += (nm) * _f.x; a1 += (nm) * _f.y; \
        _f = __half22float2(*reinterpret_cast<const __half2*>(&(r).y)); a2 += (nm) * _f.x; a3 += (nm) * _f.y; \
        _f = __half22float2(*reinterpret_cast<const __half2*>(&(r).z)); a4 += (nm) * _f.x; a5 += (nm) * _f.y; \
        _f = __half22float2(*reinterpret_cast<const __half2*>(&(r).w)); a6 += (nm) * _f.x; a7 += (nm) * _f.y; \
    } while (0)

    for (int j0 = beg; j0 < end; j0 += 32) {
        int j = j0 + lane;
        if (j < end) stage[wi][lane] = g_csr[j];
        __syncwarp();
        int cnt = end - j0; if (cnt > 32) cnt = 32;
        int i = 0;
        for (; i + 8 <= cnt; i += 8) {      // 2 groups of 4 edges, 2 LDGs in flight
            int2 e0 = stage[wi][i + h];
            int2 e1 = stage[wi][i + 4 + h];
            uint4 r0 = *reinterpret_cast<const uint4*>(h1b + e0.x);
            uint4 r1 = *reinterpret_cast<const uint4*>(h1b + e1.x);
            float n0 = __int_as_float(e0.y);
            float n1 = __int_as_float(e1.y);
            ACC8(r0, n0);
            ACC8(r1, n1);
        }
        for (; i + 4 <= cnt; i += 4) {
            int2 e0 = stage[wi][i + h];
            uint4 r0 = *reinterpret_cast<const uint4*>(h1b + e0.x);
            float n0 = __int_as_float(e0.y);
            ACC8(r0, n0);
        }
        if (i < cnt) {                      // 1..3 leftover edges
            int idx = i + h;
            int2 e0 = stage[wi][idx < cnt ? idx : i];   // safe address
            float n0 = (idx < cnt) ? __int_as_float(e0.y) : 0.f;
            uint4 r0 = *reinterpret_cast<const uint4*>(h1b + e0.x);
            ACC8(r0, n0);
        }
        __syncwarp();
    }
#undef ACC8

    // combine the 4 edge subgroups (lanes differing in bits 3,4)
#pragma unroll
    for (int o = 8; o <= 16; o <<= 1) {
        a0 += __shfl_xor_sync(0xFFFFFFFFu, a0, o);
        a1 += __shfl_xor_sync(0xFFFFFFFFu, a1, o);
        a2 += __shfl_xor_sync(0xFFFFFFFFu, a2, o);
        a3 += __shfl_xor_sync(0xFFFFFFFFu, a3, o);
        a4 += __shfl_xor_sync(0xFFFFFFFFu, a4, o);
        a5 += __shfl_xor_sync(0xFFFFFFFFu, a5, o);
        a6 += __shfl_xor_sync(0xFFFFFFFFu, a6, o);
        a7 += __shfl_xor_sync(0xFFFFFFFFu, a7, o);
    }

    // epilogue: this lane owns cols 8q..8q+7
    float p0 = 0.f, p1 = 0.f;
    float acc[8] = {a0, a1, a2, a3, a4, a5, a6, a7};
#pragma unroll
    for (int k = 0; k < 8; k++) {
        int col = 8 * q + k;
        float hv = fmaxf(dv * acc[k] + b1[col], 0.f);
        p0 += hv * W2[col * 2 + 0];
        p1 += hv * W2[col * 2 + 1];
    }
#pragma unroll
    for (int o = 4; o > 0; o >>= 1) {
        p0 += __shfl_xor_sync(0xFFFFFFFFu, p0, o);
        p1 += __shfl_xor_sync(0xFFFFFFFFu, p1, o);
    }
    if (lane == 0) {
        g_h2[w * 2 + 0] = dv * p0;   // h2' = dinv * h2
        g_h2[w * 2 + 1] = dv * p1;
    }
}

// ---------------- agg2: A = dv*(Σ ew*h2'[src] + h2'[w]) + b2; log_softmax ----------------
__global__ void __launch_bounds__(256) k_agg2(const float* __restrict__ b2,
                                              float* __restrict__ out, int n) {
    int w = (blockIdx.x * blockDim.x + threadIdx.x) >> 5;
    int lane = threadIdx.x & 31;
    if (w >= n) return;
    int2 seg = g_seg[w];
    const char* h2b = reinterpret_cast<const char*>(g_h2);
    float a0 = 0.f, a1 = 0.f;
    for (int j = seg.x + lane; j < seg.y; j += 32) {
        int2 e = g_csr[j];
        float nm = __int_as_float(e.y);
        // e.x = src<<7; h2 byte offset = src*8 = e.x>>4
        float2 v = *reinterpret_cast<const float2*>(h2b + (e.x >> 4));
        a0 += nm * v.x;
        a1 += nm * v.y;
    }
#pragma unroll
    for (int o = 16; o > 0; o >>= 1) {
        a0 += __shfl_xor_sync(0xFFFFFFFFu, a0, o);
        a1 += __shfl_xor_sync(0xFFFFFFFFu, a1, o);
    }
    if (lane == 0) {
        float dv = g_dinv[w];
        float2 hv = *reinterpret_cast<const float2*>(g_h2 + (size_t)w * 2);
        float A = dv * (a0 + hv.x) + b2[0];
        float B = dv * (a1 + hv.y) + b2[1];
        float m = fmaxf(A, B);
        float lse = m + logf(expf(A - m) + expf(B - m));
        out[w * 2 + 0] = A - lse;
        out[w * 2 + 1] = B - lse;
    }
}

extern "C" void kernel_launch(void* const* d_in, const int* in_sizes, int n_in,
                              void* d_out, int out_size) {
    const float* x  = (const float*)d_in[0];
    const int*   ei = (const int*)d_in[1];   // int32 (JAX x64 disabled)
    const float* ew = (const float*)d_in[2];
    const float* W1 = (const float*)d_in[3];
    const float* b1 = (const float*)d_in[4];
    const float* W2 = (const float*)d_in[5];
    const float* b2 = (const float*)d_in[6];
    float* out = (float*)d_out;

    const int n  = in_sizes[0] / F_IN;   // 100000
    const int ne = in_sizes[2];          // 3200000

    const int nq = (ne + 3) / 4;                   // 4 edges per edge-stream thread
    const int nblk_ed = (nq + 255) / 256;
    const int nblk_gm = (n + 31) / 32;
    k_scatter<<<nblk_ed, 256>>>(ei, ew, ne);
    k_base<<<(n + 255) / 256, 256>>>(n);
    k_gemm_fill<<<nblk_gm + nblk_ed, 256>>>(ei, ew, x, W1, n, ne, nblk_gm);
    k_agg1<<<(n + 7) / 8, 256>>>(W2, b1, n);
    k_agg2<<<(n * 32 + 255) / 256, 256>>>(b2, out, n);
}

// round 16
// speedup vs baseline: 1.1340x; 1.1340x over previous
#include <cuda_runtime.h>
#include <cuda_fp16.h>
#include <cuda_bf16.h>

#define N_NODES 100000
#define N_EDGES 3200000
#define F_IN 35
#define KPAD 36
#define F_HID 64
#define F_OUT 2
#define FIXP 268435456.0f   // 2^28
#define FIXP_INV (1.0f / 268435456.0f)

// ---- scratch (static; no allocation allowed; zero-initialized at load) ----
__device__ __align__(16) __half g_h1[N_NODES * F_HID];  // dinv * (x@W1), fp16, row-major
__device__ __align__(16) float  g_h2[N_NODES * F_OUT];  // dinv * (layer-2 features)
__device__ unsigned long long g_acc[N_NODES];  // hi24: count, lo40: sum(ew)*2^28 (self-cleaned)
__device__ float g_dinv[N_NODES];
__device__ __align__(8) int2 g_seg[N_NODES];   // (beg, end) of node's CSR segment
__device__ int   g_cursor;                     // CSR cursor (self-cleaned by k_gemm_fill)
__device__ __align__(16) int g_rank[N_EDGES];  // per-edge slot within its dst segment
__device__ __align__(8) int2 g_csr[N_EDGES];   // (src, ew bits)

// ---------------- edge scatter (4 edges/thread): counts + weighted degree + rank ----
__global__ void __launch_bounds__(256) k_scatter(const int* __restrict__ ei,
                                                 const float* __restrict__ ew, int ne) {
    int e0 = (blockIdx.x * 256 + threadIdx.x) * 4;
    if (e0 + 3 < ne) {
        float4 w4 = *reinterpret_cast<const float4*>(ew + e0);  // e0 % 4 == 0
        int d0 = ei[ne + e0], d1 = ei[ne + e0 + 1];
        int d2 = ei[ne + e0 + 2], d3 = ei[ne + e0 + 3];
        unsigned long long o0 = atomicAdd(&g_acc[d0], (1ULL << 40) | (unsigned long long)(w4.x * FIXP));
        unsigned long long o1 = atomicAdd(&g_acc[d1], (1ULL << 40) | (unsigned long long)(w4.y * FIXP));
        unsigned long long o2 = atomicAdd(&g_acc[d2], (1ULL << 40) | (unsigned long long)(w4.z * FIXP));
        unsigned long long o3 = atomicAdd(&g_acc[d3], (1ULL << 40) | (unsigned long long)(w4.w * FIXP));
        *reinterpret_cast<int4*>(g_rank + e0) =
            make_int4((int)(o0 >> 40), (int)(o1 >> 40), (int)(o2 >> 40), (int)(o3 >> 40));
    } else {
        for (int e = e0; e < ne; e++) {
            int dst = ei[ne + e];
            unsigned long long old = atomicAdd(&g_acc[dst],
                (1ULL << 40) | (unsigned long long)(ew[e] * FIXP));
            g_rank[e] = (int)(old >> 40);
        }
    }
}

// ---- base: dinv + seg alloc (block scan + cursor atomic) + acc self-clean ----
__global__ void __launch_bounds__(256) k_base(int n) {
    __shared__ int swarp[8];
    __shared__ int sbase;
    int t = threadIdx.x, lane = t & 31, wid = t >> 5;
    int i = blockIdx.x * 256 + t;
    int c = 0;
    if (i < n) {
        unsigned long long a = g_acc[i];
        g_acc[i] = 0ULL;                    // self-clean for next replay
        c = (int)(a >> 40);
        float deg = 1.0f + (float)(a & ((1ULL << 40) - 1)) * FIXP_INV;
        g_dinv[i] = rsqrtf(deg);
    }
    int v = c;
#pragma unroll
    for (int o = 1; o < 32; o <<= 1) {
        int u = __shfl_up_sync(0xFFFFFFFFu, v, o);
        if (lane >= o) v += u;
    }
    if (lane == 31) swarp[wid] = v;
    __syncthreads();
    if (wid == 0) {
        int s = (lane < 8) ? swarp[lane] : 0;
#pragma unroll
        for (int o = 1; o < 8; o <<= 1) {
            int u = __shfl_up_sync(0xFFFFFFFFu, s, o);
            if (lane >= o) s += u;
        }
        if (lane < 8) swarp[lane] = s;
        if (lane == 7) sbase = atomicAdd(&g_cursor, s);
    }
    __syncthreads();
    int excl = v - c + (wid > 0 ? swarp[wid - 1] : 0);
    if (i < n) {
        int beg = sbase + excl;
        g_seg[i] = make_int2(beg, beg + c);
    }
}

// ---------------- fused: layer-1 GEMM (4 rows/warp, 2 cols/lane) || CSR fill ----
__global__ void __launch_bounds__(256) k_gemm_fill(
        const int* __restrict__ ei, const float* __restrict__ ew,
        const float* __restrict__ x, const float* __restrict__ W1,
        int n, int ne, int nblk_gm) {
    __shared__ float2 sW2[KPAD][32];      // [k][lane] -> cols (2l, 2l+1)
    __shared__ float  sx[8][4][KPAD];

    if (blockIdx.x >= (unsigned)nblk_gm) {
        // ---- CSR fill part (4 edges/thread): (src, ew) ----
        if (blockIdx.x == (unsigned)nblk_gm && threadIdx.x == 0)
            g_cursor = 0;   // self-clean for next replay
        int e0 = ((blockIdx.x - nblk_gm) * 256 + threadIdx.x) * 4;
        if (e0 + 3 < ne) {
            int4   s4 = *reinterpret_cast<const int4*>(ei + e0);       // e0 % 4 == 0
            float4 w4 = *reinterpret_cast<const float4*>(ew + e0);
            int4   r4 = *reinterpret_cast<const int4*>(g_rank + e0);
            int d0 = ei[ne + e0], d1 = ei[ne + e0 + 1];
            int d2 = ei[ne + e0 + 2], d3 = ei[ne + e0 + 3];
            g_csr[g_seg[d0].x + r4.x] = make_int2(s4.x, __float_as_int(w4.x));
            g_csr[g_seg[d1].x + r4.y] = make_int2(s4.y, __float_as_int(w4.y));
            g_csr[g_seg[d2].x + r4.z] = make_int2(s4.z, __float_as_int(w4.z));
            g_csr[g_seg[d3].x + r4.w] = make_int2(s4.w, __float_as_int(w4.w));
        } else {
            for (int e = e0; e < ne; e++) {
                int src = ei[e];
                int dst = ei[ne + e];
                g_csr[g_seg[dst].x + g_rank[e]] = make_int2(src, __float_as_int(ew[e]));
            }
        }
        return;
    }

    // ---- gemm1 part: h1' = dinv[row] * (x[row] @ W1), 4 rows/warp, 2 cols/lane ----
    int t = threadIdx.x, w = t >> 5, lane = t & 31;
    for (int i = t; i < KPAD * 32; i += 256) {
        int k = i >> 5, l = i & 31;
        float2 v = make_float2(0.f, 0.f);
        if (k < F_IN) { v.x = W1[k * F_HID + 2 * l]; v.y = W1[k * F_HID + 2 * l + 1]; }
        sW2[k][l] = v;
    }
    int row0 = blockIdx.x * 32 + w * 4;
#pragma unroll
    for (int r = 0; r < 4; r++) {
        int row = row0 + r;
        if (row < n) {
            sx[w][r][lane] = x[(size_t)row * F_IN + lane];
            if (lane < 4) sx[w][r][32 + lane] =
                (lane < F_IN - 32) ? x[(size_t)row * F_IN + 32 + lane] : 0.f;
        }
    }
    __syncthreads();
    if (row0 >= n) return;

    float a0x = 0.f, a0y = 0.f, a1x = 0.f, a1y = 0.f;
    float a2x = 0.f, a2y = 0.f, a3x = 0.f, a3y = 0.f;
    const float4* sx0 = reinterpret_cast<const float4*>(sx[w][0]);
    const float4* sx1 = reinterpret_cast<const float4*>(sx[w][1]);
    const float4* sx2 = reinterpret_cast<const float4*>(sx[w][2]);
    const float4* sx3 = reinterpret_cast<const float4*>(sx[w][3]);
#pragma unroll
    for (int k4 = 0; k4 < KPAD / 4; k4++) {
        float4 x0 = sx0[k4], x1 = sx1[k4], x2 = sx2[k4], x3 = sx3[k4];
#pragma unroll
        for (int i = 0; i < 4; i++) {
            float2 wv = sW2[k4 * 4 + i][lane];
            float v0 = (&x0.x)[i], v1 = (&x1.x)[i], v2 = (&x2.x)[i], v3 = (&x3.x)[i];
            a0x += v0 * wv.x; a0y += v0 * wv.y;
            a1x += v1 * wv.x; a1y += v1 * wv.y;
            a2x += v2 * wv.x; a2y += v2 * wv.y;
            a3x += v3 * wv.x; a3y += v3 * wv.y;
        }
    }
    {
        float dv = g_dinv[row0];
        reinterpret_cast<__half2*>(g_h1 + (size_t)row0 * F_HID)[lane] =
            __floats2half2_rn(dv * a0x, dv * a0y);
    }
    if (row0 + 1 < n) {
        float dv = g_dinv[row0 + 1];
        reinterpret_cast<__half2*>(g_h1 + (size_t)(row0 + 1) * F_HID)[lane] =
            __floats2half2_rn(dv * a1x, dv * a1y);
    }
    if (row0 + 2 < n) {
        float dv = g_dinv[row0 + 2];
        reinterpret_cast<__half2*>(g_h1 + (size_t)(row0 + 2) * F_HID)[lane] =
            __floats2half2_rn(dv * a2x, dv * a2y);
    }
    if (row0 + 3 < n) {
        float dv = g_dinv[row0 + 3];
        reinterpret_cast<__half2*>(g_h1 + (size_t)(row0 + 3) * F_HID)[lane] =
            __floats2half2_rn(dv * a3x, dv * a3y);
    }
}

// ---- agg1 (R12-verified): warp/node, 4B/lane gather, unroll 8 + relu + b1 + W2 GEMV ----
__global__ void __launch_bounds__(256) k_agg1(const float* __restrict__ W2,
                                              const float* __restrict__ b1, int n) {
    __shared__ int2 stage[8][32];
    int wi = threadIdx.x >> 5;
    int lane = threadIdx.x & 31;
    int w = blockIdx.x * 8 + wi;
    if (w >= n) return;
    int2 seg = g_seg[w];
    int beg = seg.x, end = seg.y;
    float dv = g_dinv[w];

    float2 self = __half22float2(
        reinterpret_cast<const __half2*>(g_h1 + (size_t)w * F_HID)[lane]);
    float ax = self.x, ay = self.y;   // h1'[w] = dv*h1[w]; x dv below gives dv^2*h1

    for (int j0 = beg; j0 < end; j0 += 32) {
        int j = j0 + lane;
        if (j < end) stage[wi][lane] = g_csr[j];
        __syncwarp();
        int cnt = end - j0; if (cnt > 32) cnt = 32;
        int i = 0;
        for (; i + 8 <= cnt; i += 8) {
            int2 e0 = stage[wi][i];
            int2 e1 = stage[wi][i + 1];
            int2 e2 = stage[wi][i + 2];
            int2 e3 = stage[wi][i + 3];
            int2 e4 = stage[wi][i + 4];
            int2 e5 = stage[wi][i + 5];
            int2 e6 = stage[wi][i + 6];
            int2 e7 = stage[wi][i + 7];
            float2 f0 = __half22float2(reinterpret_cast<const __half2*>(g_h1 + (size_t)e0.x * F_HID)[lane]);
            float2 f1 = __half22float2(reinterpret_cast<const __half2*>(g_h1 + (size_t)e1.x * F_HID)[lane]);
            float2 f2 = __half22float2(reinterpret_cast<const __half2*>(g_h1 + (size_t)e2.x * F_HID)[lane]);
            float2 f3 = __half22float2(reinterpret_cast<const __half2*>(g_h1 + (size_t)e3.x * F_HID)[lane]);
            float2 f4 = __half22float2(reinterpret_cast<const __half2*>(g_h1 + (size_t)e4.x * F_HID)[lane]);
            float2 f5 = __half22float2(reinterpret_cast<const __half2*>(g_h1 + (size_t)e5.x * F_HID)[lane]);
            float2 f6 = __half22float2(reinterpret_cast<const __half2*>(g_h1 + (size_t)e6.x * F_HID)[lane]);
            float2 f7 = __half22float2(reinterpret_cast<const __half2*>(g_h1 + (size_t)e7.x * F_HID)[lane]);
            ax += __int_as_float(e0.y) * f0.x; ay += __int_as_float(e0.y) * f0.y;
            ax += __int_as_float(e1.y) * f1.x; ay += __int_as_float(e1.y) * f1.y;
            ax += __int_as_float(e2.y) * f2.x; ay += __int_as_float(e2.y) * f2.y;
            ax += __int_as_float(e3.y) * f3.x; ay += __int_as_float(e3.y) * f3.y;
            ax += __int_as_float(e4.y) * f4.x; ay += __int_as_float(e4.y) * f4.y;
            ax += __int_as_float(e5.y) * f5.x; ay += __int_as_float(e5.y) * f5.y;
            ax += __int_as_float(e6.y) * f6.x; ay += __int_as_float(e6.y) * f6.y;
            ax += __int_as_float(e7.y) * f7.x; ay += __int_as_float(e7.y) * f7.y;
        }
        for (; i < cnt; i++) {
            int2 e0 = stage[wi][i];
            float2 f0 = __half22float2(reinterpret_cast<const __half2*>(g_h1 + (size_t)e0.x * F_HID)[lane]);
            float n0 = __int_as_float(e0.y);
            ax += n0 * f0.x; ay += n0 * f0.y;
        }
        __syncwarp();
    }

    ax *= dv;
    ay *= dv;

    float h0 = fmaxf(ax + b1[2 * lane],     0.f);
    float h1 = fmaxf(ay + b1[2 * lane + 1], 0.f);
    float p0 = h0 * W2[(2 * lane) * 2 + 0] + h1 * W2[(2 * lane + 1) * 2 + 0];
    float p1 = h0 * W2[(2 * lane) * 2 + 1] + h1 * W2[(2 * lane + 1) * 2 + 1];
#pragma unroll
    for (int o = 16; o > 0; o >>= 1) {
        p0 += __shfl_xor_sync(0xFFFFFFFFu, p0, o);
        p1 += __shfl_xor_sync(0xFFFFFFFFu, p1, o);
    }
    if (lane == 0) {
        g_h2[w * 2 + 0] = dv * p0;   // h2' = dinv * h2
        g_h2[w * 2 + 1] = dv * p1;
    }
}

// ---------------- agg2: A = dv*(Σ ew*h2'[src] + h2'[w]) + b2; log_softmax ----------------
__global__ void __launch_bounds__(256) k_agg2(const float* __restrict__ b2,
                                              float* __restrict__ out, int n) {
    int w = (blockIdx.x * blockDim.x + threadIdx.x) >> 5;
    int lane = threadIdx.x & 31;
    if (w >= n) return;
    int2 seg = g_seg[w];
    float a0 = 0.f, a1 = 0.f;
    for (int j = seg.x + lane; j < seg.y; j += 32) {
        int2 e = g_csr[j];
        float nm = __int_as_float(e.y);
        float2 v = *reinterpret_cast<const float2*>(g_h2 + (size_t)e.x * 2);
        a0 += nm * v.x;
        a1 += nm * v.y;
    }
#pragma unroll
    for (int o = 16; o > 0; o >>= 1) {
        a0 += __shfl_xor_sync(0xFFFFFFFFu, a0, o);
        a1 += __shfl_xor_sync(0xFFFFFFFFu, a1, o);
    }
    if (lane == 0) {
        float dv = g_dinv[w];
        float2 hv = *reinterpret_cast<const float2*>(g_h2 + (size_t)w * 2);
        float A = dv * (a0 + hv.x) + b2[0];
        float B = dv * (a1 + hv.y) + b2[1];
        float m = fmaxf(A, B);
        float lse = m + logf(expf(A - m) + expf(B - m));
        out[w * 2 + 0] = A - lse;
        out[w * 2 + 1] = B - lse;
    }
}

extern "C" void kernel_launch(void* const* d_in, const int* in_sizes, int n_in,
                              void* d_out, int out_size) {
    const float* x  = (const float*)d_in[0];
    const int*   ei = (const int*)d_in[1];   // int32 (JAX x64 disabled)
    const float* ew = (const float*)d_in[2];
    const float* W1 = (const float*)d_in[3];
    const float* b1 = (const float*)d_in[4];
    const float* W2 = (const float*)d_in[5];
    const float* b2 = (const float*)d_in[6];
    float* out = (float*)d_out;

    const int n  = in_sizes[0] / F_IN;   // 100000
    const int ne = in_sizes[2];          // 3200000

    const int nq = (ne + 3) / 4;                   // 4 edges per edge-stream thread
    const int nblk_ed = (nq + 255) / 256;
    const int nblk_gm = (n + 31) / 32;
    k_scatter<<<nblk_ed, 256>>>(ei, ew, ne);
    k_base<<<(n + 255) / 256, 256>>>(n);
    k_gemm_fill<<<nblk_gm + nblk_ed, 256>>>(ei, ew, x, W1, n, ne, nblk_gm);
    k_agg1<<<(n + 7) / 8, 256>>>(W2, b1, n);
    k_agg2<<<(n * 32 + 255) / 256, 256>>>(b2, out, n);
}

// round 17
// speedup vs baseline: 1.2171x; 1.0733x over previous
#include <cuda_runtime.h>
#include <cuda_fp16.h>
#include <cuda_bf16.h>

#define N_NODES 100000
#define N_EDGES 3200000
#define F_IN 35
#define KPAD 36
#define F_HID 64
#define F_OUT 2
#define FIXP 268435456.0f   // 2^28
#define FIXP_INV (1.0f / 268435456.0f)

// ---- scratch (static; no allocation allowed; zero-initialized at load) ----
__device__ __align__(16) __half g_h1[N_NODES * F_HID];  // dinv * (x@W1), fp16, row-major
__device__ __align__(16) float  g_h2[N_NODES * F_OUT];  // dinv * (layer-2 features)
__device__ unsigned long long g_acc[N_NODES];  // hi24: count, lo40: sum(ew)*2^28 (self-cleaned)
__device__ float g_dinv[N_NODES];
__device__ __align__(8) int2 g_seg[N_NODES];   // (beg, end) of node's CSR segment
__device__ int   g_cursor;                     // CSR cursor (self-cleaned by k_gemm_fill)
__device__ __align__(16) int g_rank[N_EDGES];  // per-edge slot within its dst segment
__device__ __align__(8) int2 g_csr[N_EDGES];   // (src, ew bits)

// ---------------- edge scatter (4 edges/thread): counts + weighted degree + rank ----
__global__ void __launch_bounds__(256) k_scatter(const int* __restrict__ ei,
                                                 const float* __restrict__ ew, int ne) {
    int e0 = (blockIdx.x * 256 + threadIdx.x) * 4;
    if (e0 + 3 < ne) {
        float4 w4 = *reinterpret_cast<const float4*>(ew + e0);  // e0 % 4 == 0
        int d0 = ei[ne + e0], d1 = ei[ne + e0 + 1];
        int d2 = ei[ne + e0 + 2], d3 = ei[ne + e0 + 3];
        unsigned long long o0 = atomicAdd(&g_acc[d0], (1ULL << 40) | (unsigned long long)(w4.x * FIXP));
        unsigned long long o1 = atomicAdd(&g_acc[d1], (1ULL << 40) | (unsigned long long)(w4.y * FIXP));
        unsigned long long o2 = atomicAdd(&g_acc[d2], (1ULL << 40) | (unsigned long long)(w4.z * FIXP));
        unsigned long long o3 = atomicAdd(&g_acc[d3], (1ULL << 40) | (unsigned long long)(w4.w * FIXP));
        *reinterpret_cast<int4*>(g_rank + e0) =
            make_int4((int)(o0 >> 40), (int)(o1 >> 40), (int)(o2 >> 40), (int)(o3 >> 40));
    } else {
        for (int e = e0; e < ne; e++) {
            int dst = ei[ne + e];
            unsigned long long old = atomicAdd(&g_acc[dst],
                (1ULL << 40) | (unsigned long long)(ew[e] * FIXP));
            g_rank[e] = (int)(old >> 40);
        }
    }
}

// ---- base: dinv + seg alloc (block scan + cursor atomic) + acc self-clean ----
__global__ void __launch_bounds__(256) k_base(int n) {
    cudaGridDependencySynchronize();   // wait for k_scatter's atomics
    __shared__ int swarp[8];
    __shared__ int sbase;
    int t = threadIdx.x, lane = t & 31, wid = t >> 5;
    int i = blockIdx.x * 256 + t;
    int c = 0;
    if (i < n) {
        unsigned long long a = g_acc[i];
        g_acc[i] = 0ULL;                    // self-clean for next replay
        c = (int)(a >> 40);
        float deg = 1.0f + (float)(a & ((1ULL << 40) - 1)) * FIXP_INV;
        g_dinv[i] = rsqrtf(deg);
    }
    int v = c;
#pragma unroll
    for (int o = 1; o < 32; o <<= 1) {
        int u = __shfl_up_sync(0xFFFFFFFFu, v, o);
        if (lane >= o) v += u;
    }
    if (lane == 31) swarp[wid] = v;
    __syncthreads();
    if (wid == 0) {
        int s = (lane < 8) ? swarp[lane] : 0;
#pragma unroll
        for (int o = 1; o < 8; o <<= 1) {
            int u = __shfl_up_sync(0xFFFFFFFFu, s, o);
            if (lane >= o) s += u;
        }
        if (lane < 8) swarp[lane] = s;
        if (lane == 7) sbase = atomicAdd(&g_cursor, s);
    }
    __syncthreads();
    int excl = v - c + (wid > 0 ? swarp[wid - 1] : 0);
    if (i < n) {
        int beg = sbase + excl;
        g_seg[i] = make_int2(beg, beg + c);
    }
}

// ---------------- fused: layer-1 GEMM (4 rows/warp, 2 cols/lane) || CSR fill ----
__global__ void __launch_bounds__(256) k_gemm_fill(
        const int* __restrict__ ei, const float* __restrict__ ew,
        const float* __restrict__ x, const float* __restrict__ W1,
        int n, int ne, int nblk_gm) {
    __shared__ float2 sW2[KPAD][32];      // [k][lane] -> cols (2l, 2l+1)
    __shared__ float  sx[8][4][KPAD];

    if (blockIdx.x >= (unsigned)nblk_gm) {
        // ---- CSR fill part (4 edges/thread): (src, ew) ----
        cudaGridDependencySynchronize();   // wait for k_base (seg, cursor consumed)
        if (blockIdx.x == (unsigned)nblk_gm && threadIdx.x == 0)
            g_cursor = 0;   // self-clean for next replay
        int e0 = ((blockIdx.x - nblk_gm) * 256 + threadIdx.x) * 4;
        if (e0 + 3 < ne) {
            int4   s4 = *reinterpret_cast<const int4*>(ei + e0);       // e0 % 4 == 0
            float4 w4 = *reinterpret_cast<const float4*>(ew + e0);
            int4   r4 = *reinterpret_cast<const int4*>(g_rank + e0);
            int d0 = ei[ne + e0], d1 = ei[ne + e0 + 1];
            int d2 = ei[ne + e0 + 2], d3 = ei[ne + e0 + 3];
            g_csr[g_seg[d0].x + r4.x] = make_int2(s4.x, __float_as_int(w4.x));
            g_csr[g_seg[d1].x + r4.y] = make_int2(s4.y, __float_as_int(w4.y));
            g_csr[g_seg[d2].x + r4.z] = make_int2(s4.z, __float_as_int(w4.z));
            g_csr[g_seg[d3].x + r4.w] = make_int2(s4.w, __float_as_int(w4.w));
        } else {
            for (int e = e0; e < ne; e++) {
                int src = ei[e];
                int dst = ei[ne + e];
                g_csr[g_seg[dst].x + g_rank[e]] = make_int2(src, __float_as_int(ew[e]));
            }
        }
        return;
    }

    // ---- gemm1 part: independent prologue (x, W1 staging) overlaps k_base via PDL ----
    int t = threadIdx.x, w = t >> 5, lane = t & 31;
    for (int i = t; i < KPAD * 32; i += 256) {
        int k = i >> 5, l = i & 31;
        float2 v = make_float2(0.f, 0.f);
        if (k < F_IN) { v.x = W1[k * F_HID + 2 * l]; v.y = W1[k * F_HID + 2 * l + 1]; }
        sW2[k][l] = v;
    }
    int row0 = blockIdx.x * 32 + w * 4;
#pragma unroll
    for (int r = 0; r < 4; r++) {
        int row = row0 + r;
        if (row < n) {
            sx[w][r][lane] = x[(size_t)row * F_IN + lane];
            if (lane < 4) sx[w][r][32 + lane] =
                (lane < F_IN - 32) ? x[(size_t)row * F_IN + 32 + lane] : 0.f;
        }
    }
    __syncthreads();
    if (row0 >= n) return;

    float a0x = 0.f, a0y = 0.f, a1x = 0.f, a1y = 0.f;
    float a2x = 0.f, a2y = 0.f, a3x = 0.f, a3y = 0.f;
    const float4* sx0 = reinterpret_cast<const float4*>(sx[w][0]);
    const float4* sx1 = reinterpret_cast<const float4*>(sx[w][1]);
    const float4* sx2 = reinterpret_cast<const float4*>(sx[w][2]);
    const float4* sx3 = reinterpret_cast<const float4*>(sx[w][3]);
#pragma unroll
    for (int k4 = 0; k4 < KPAD / 4; k4++) {
        float4 x0 = sx0[k4], x1 = sx1[k4], x2 = sx2[k4], x3 = sx3[k4];
#pragma unroll
        for (int i = 0; i < 4; i++) {
            float2 wv = sW2[k4 * 4 + i][lane];
            float v0 = (&x0.x)[i], v1 = (&x1.x)[i], v2 = (&x2.x)[i], v3 = (&x3.x)[i];
            a0x += v0 * wv.x; a0y += v0 * wv.y;
            a1x += v1 * wv.x; a1y += v1 * wv.y;
            a2x += v2 * wv.x; a2y += v2 * wv.y;
            a3x += v3 * wv.x; a3y += v3 * wv.y;
        }
    }
    cudaGridDependencySynchronize();   // need g_dinv from k_base only here
    {
        float dv = g_dinv[row0];
        reinterpret_cast<__half2*>(g_h1 + (size_t)row0 * F_HID)[lane] =
            __floats2half2_rn(dv * a0x, dv * a0y);
    }
    if (row0 + 1 < n) {
        float dv = g_dinv[row0 + 1];
        reinterpret_cast<__half2*>(g_h1 + (size_t)(row0 + 1) * F_HID)[lane] =
            __floats2half2_rn(dv * a1x, dv * a1y);
    }
    if (row0 + 2 < n) {
        float dv = g_dinv[row0 + 2];
        reinterpret_cast<__half2*>(g_h1 + (size_t)(row0 + 2) * F_HID)[lane] =
            __floats2half2_rn(dv * a2x, dv * a2y);
    }
    if (row0 + 3 < n) {
        float dv = g_dinv[row0 + 3];
        reinterpret_cast<__half2*>(g_h1 + (size_t)(row0 + 3) * F_HID)[lane] =
            __floats2half2_rn(dv * a3x, dv * a3y);
    }
}

// ---- agg1 (R12-verified): warp/node, 4B/lane gather, unroll 8 + relu + b1 + W2 GEMV ----
__global__ void __launch_bounds__(256) k_agg1(const float* __restrict__ W2,
                                              const float* __restrict__ b1, int n) {
    cudaGridDependencySynchronize();   // wait for k_gemm_fill (h1, csr)
    __shared__ int2 stage[8][32];
    int wi = threadIdx.x >> 5;
    int lane = threadIdx.x & 31;
    int w = blockIdx.x * 8 + wi;
    if (w >= n) return;
    int2 seg = g_seg[w];
    int beg = seg.x, end = seg.y;
    float dv = g_dinv[w];

    float2 self = __half22float2(
        reinterpret_cast<const __half2*>(g_h1 + (size_t)w * F_HID)[lane]);
    float ax = self.x, ay = self.y;   // h1'[w] = dv*h1[w]; x dv below gives dv^2*h1

    for (int j0 = beg; j0 < end; j0 += 32) {
        int j = j0 + lane;
        if (j < end) stage[wi][lane] = g_csr[j];
        __syncwarp();
        int cnt = end - j0; if (cnt > 32) cnt = 32;
        int i = 0;
        for (; i + 8 <= cnt; i += 8) {
            int2 e0 = stage[wi][i];
            int2 e1 = stage[wi][i + 1];
            int2 e2 = stage[wi][i + 2];
            int2 e3 = stage[wi][i + 3];
            int2 e4 = stage[wi][i + 4];
            int2 e5 = stage[wi][i + 5];
            int2 e6 = stage[wi][i + 6];
            int2 e7 = stage[wi][i + 7];
            float2 f0 = __half22float2(reinterpret_cast<const __half2*>(g_h1 + (size_t)e0.x * F_HID)[lane]);
            float2 f1 = __half22float2(reinterpret_cast<const __half2*>(g_h1 + (size_t)e1.x * F_HID)[lane]);
            float2 f2 = __half22float2(reinterpret_cast<const __half2*>(g_h1 + (size_t)e2.x * F_HID)[lane]);
            float2 f3 = __half22float2(reinterpret_cast<const __half2*>(g_h1 + (size_t)e3.x * F_HID)[lane]);
            float2 f4 = __half22float2(reinterpret_cast<const __half2*>(g_h1 + (size_t)e4.x * F_HID)[lane]);
            float2 f5 = __half22float2(reinterpret_cast<const __half2*>(g_h1 + (size_t)e5.x * F_HID)[lane]);
            float2 f6 = __half22float2(reinterpret_cast<const __half2*>(g_h1 + (size_t)e6.x * F_HID)[lane]);
            float2 f7 = __half22float2(reinterpret_cast<const __half2*>(g_h1 + (size_t)e7.x * F_HID)[lane]);
            ax += __int_as_float(e0.y) * f0.x; ay += __int_as_float(e0.y) * f0.y;
            ax += __int_as_float(e1.y) * f1.x; ay += __int_as_float(e1.y) * f1.y;
            ax += __int_as_float(e2.y) * f2.x; ay += __int_as_float(e2.y) * f2.y;
            ax += __int_as_float(e3.y) * f3.x; ay += __int_as_float(e3.y) * f3.y;
            ax += __int_as_float(e4.y) * f4.x; ay += __int_as_float(e4.y) * f4.y;
            ax += __int_as_float(e5.y) * f5.x; ay += __int_as_float(e5.y) * f5.y;
            ax += __int_as_float(e6.y) * f6.x; ay += __int_as_float(e6.y) * f6.y;
            ax += __int_as_float(e7.y) * f7.x; ay += __int_as_float(e7.y) * f7.y;
        }
        for (; i < cnt; i++) {
            int2 e0 = stage[wi][i];
            float2 f0 = __half22float2(reinterpret_cast<const __half2*>(g_h1 + (size_t)e0.x * F_HID)[lane]);
            float n0 = __int_as_float(e0.y);
            ax += n0 * f0.x; ay += n0 * f0.y;
        }
        __syncwarp();
    }

    ax *= dv;
    ay *= dv;

    float h0 = fmaxf(ax + b1[2 * lane],     0.f);
    float h1 = fmaxf(ay + b1[2 * lane + 1], 0.f);
    float p0 = h0 * W2[(2 * lane) * 2 + 0] + h1 * W2[(2 * lane + 1) * 2 + 0];
    float p1 = h0 * W2[(2 * lane) * 2 + 1] + h1 * W2[(2 * lane + 1) * 2 + 1];
#pragma unroll
    for (int o = 16; o > 0; o >>= 1) {
        p0 += __shfl_xor_sync(0xFFFFFFFFu, p0, o);
        p1 += __shfl_xor_sync(0xFFFFFFFFu, p1, o);
    }
    if (lane == 0) {
        g_h2[w * 2 + 0] = dv * p0;   // h2' = dinv * h2
        g_h2[w * 2 + 1] = dv * p1;
    }
}

// ---------------- agg2: A = dv*(Σ ew*h2'[src] + h2'[w]) + b2; log_softmax ----------------
__global__ void __launch_bounds__(256) k_agg2(const float* __restrict__ b2,
                                              float* __restrict__ out, int n) {
    cudaGridDependencySynchronize();   // wait for k_agg1 (h2)
    int w = (blockIdx.x * blockDim.x + threadIdx.x) >> 5;
    int lane = threadIdx.x & 31;
    if (w >= n) return;
    int2 seg = g_seg[w];
    float a0 = 0.f, a1 = 0.f;
    for (int j = seg.x + lane; j < seg.y; j += 32) {
        int2 e = g_csr[j];
        float nm = __int_as_float(e.y);
        float2 v = *reinterpret_cast<const float2*>(g_h2 + (size_t)e.x * 2);
        a0 += nm * v.x;
        a1 += nm * v.y;
    }
#pragma unroll
    for (int o = 16; o > 0; o >>= 1) {
        a0 += __shfl_xor_sync(0xFFFFFFFFu, a0, o);
        a1 += __shfl_xor_sync(0xFFFFFFFFu, a1, o);
    }
    if (lane == 0) {
        float dv = g_dinv[w];
        float2 hv = *reinterpret_cast<const float2*>(g_h2 + (size_t)w * 2);
        float A = dv * (a0 + hv.x) + b2[0];
        float B = dv * (a1 + hv.y) + b2[1];
        float m = fmaxf(A, B);
        float lse = m + __logf(__expf(A - m) + __expf(B - m));
        out[w * 2 + 0] = A - lse;
        out[w * 2 + 1] = B - lse;
    }
}

extern "C" void kernel_launch(void* const* d_in, const int* in_sizes, int n_in,
                              void* d_out, int out_size) {
    const float* x  = (const float*)d_in[0];
    const int*   ei = (const int*)d_in[1];   // int32 (JAX x64 disabled)
    const float* ew = (const float*)d_in[2];
    const float* W1 = (const float*)d_in[3];
    const float* b1 = (const float*)d_in[4];
    const float* W2 = (const float*)d_in[5];
    const float* b2 = (const float*)d_in[6];
    float* out = (float*)d_out;

    const int n  = in_sizes[0] / F_IN;   // 100000
    const int ne = in_sizes[2];          // 3200000

    const int nq = (ne + 3) / 4;                   // 4 edges per edge-stream thread
    const int nblk_ed = (nq + 255) / 256;
    const int nblk_gm = (n + 31) / 32;

    // PDL config: dependent launches may begin setup while the producer drains;
    // every consumer grid-syncs before touching producer data.
    cudaLaunchAttribute pdl[1];
    pdl[0].id = cudaLaunchAttributeProgrammaticStreamSerialization;
    pdl[0].val.programmaticStreamSerializationAllowed = 1;

    // 1) scatter — head of chain, normal launch
    k_scatter<<<nblk_ed, 256>>>(ei, ew, ne);

    // 2) base (PDL after scatter)
    {
        cudaLaunchConfig_t cfg = {};
        cfg.gridDim = dim3((n + 255) / 256);
        cfg.blockDim = dim3(256);
        cfg.attrs = pdl; cfg.numAttrs = 1;
        cudaLaunchKernelEx(&cfg, k_base, n);
    }
    // 3) gemm_fill (PDL after base; gemm prologue overlaps base)
    {
        cudaLaunchConfig_t cfg = {};
        cfg.gridDim = dim3(nblk_gm + nblk_ed);
        cfg.blockDim = dim3(256);
        cfg.attrs = pdl; cfg.numAttrs = 1;
        cudaLaunchKernelEx(&cfg, k_gemm_fill, ei, ew, x, W1, n, ne, nblk_gm);
    }
    // 4) agg1 (PDL after gemm_fill)
    {
        cudaLaunchConfig_t cfg = {};
        cfg.gridDim = dim3((n + 7) / 8);
        cfg.blockDim = dim3(256);
        cfg.attrs = pdl; cfg.numAttrs = 1;
        cudaLaunchKernelEx(&cfg, k_agg1, W2, b1, n);
    }
    // 5) agg2 (PDL after agg1)
    {
        cudaLaunchConfig_t cfg = {};
        cfg.gridDim = dim3((n * 32 + 255) / 256);
        cfg.blockDim = dim3(256);
        cfg.attrs = pdl; cfg.numAttrs = 1;
        cudaLaunchKernelEx(&cfg, k_agg2, b2, out, n);
    }
}